// round 4
// baseline (speedup 1.0000x reference)
#include <cuda_runtime.h>
#include <cfloat>
#include <cstdint>

// Problem constants
#define DIM   128
#define KCB   1024
#define NVEC  65536           // B*T = 16*4096
#define DECAY 0.99f
#define ONE_M_DECAY 0.01f
#define EPSV  1e-5f
#define VQ_COMMIT 0.25f

// Near-tie refinement margin (fp32 pass-1 error ~3e-4 << T << typical gap ~10)
#define TIE_MARGIN 0.05f

// GEMM tiling
#define BM 64
#define BN 64
#define XS_STRIDE 68
#define ES_STRIDE 68
#define SMEM_BYTES ((DIM*XS_STRIDE + DIM*ES_STRIDE) * 4)

// Output layout (floats), tuple order of the reference
#define OFF_Q    0
#define OFF_DIFF (NVEC*DIM)
#define OFF_CODE (OFF_DIFF + 1)
#define OFF_EMB  (OFF_CODE + NVEC)
#define OFF_CS   (OFF_EMB + DIM*KCB)
#define OFF_MEAN (OFF_CS + KCB)

// Scratch (__device__ globals; no allocations allowed)
__device__ float g_enorm[KCB];
__device__ int   g_code[NVEC];
__device__ float g_counts[KCB];
__device__ float g_emb_sum[DIM*KCB];
__device__ float g_diff;
__device__ float g_n;
__device__ int   g_nflag;
__device__ int   g_flag_rows[NVEC];

// ---------------------------------------------------------------------------
// Zero scratch (graph replayed; re-zero every launch)
// ---------------------------------------------------------------------------
__global__ void zero_kernel() {
    int i = blockIdx.x * blockDim.x + threadIdx.x;
    if (i < DIM*KCB) g_emb_sum[i] = 0.0f;
    if (i < KCB)     g_counts[i]  = 0.0f;
    if (i == 0) { g_diff = 0.0f; g_nflag = 0; }
}

// ---------------------------------------------------------------------------
// ||e_k||^2 per codebook column (pass-1 scoring only; fp32 OK)
// ---------------------------------------------------------------------------
__global__ void enorm_kernel(const float* __restrict__ E) {
    int k = blockIdx.x * blockDim.x + threadIdx.x;
    if (k >= KCB) return;
    float s = 0.0f;
#pragma unroll 8
    for (int d = 0; d < DIM; d++) {
        float v = E[(size_t)d * KCB + k];
        s += v * v;
    }
    g_enorm[k] = s;
}

// ---------------------------------------------------------------------------
// Pass 1: fp32 distance GEMM + fused top-2 argmin. Rows whose top-2 margin
// is below TIE_MARGIN are flagged for exact (fp64) refinement.
// ---------------------------------------------------------------------------
__global__ __launch_bounds__(256)
void dist_kernel(const float* __restrict__ X, const float* __restrict__ E,
                 float* __restrict__ out_code_f) {
    extern __shared__ float smem[];
    float* Xs = smem;                    // [DIM][XS_STRIDE]
    float* Es = smem + DIM * XS_STRIDE;  // [DIM][ES_STRIDE]

    const int tid = threadIdx.x;
    const int tx = tid & 15;
    const int ty = tid >> 4;
    const int n0 = blockIdx.x * BM;

    // Load X tile transposed: Xs[d][m] = X[n0+m][d]
    {
        int m  = tid >> 2;
        int dq = tid & 3;
        const float4* src = (const float4*)(X + (size_t)(n0 + m) * DIM);
#pragma unroll
        for (int it = 0; it < 8; it++) {
            int d4 = it * 4 + dq;
            float4 v = src[d4];
            int d = d4 * 4;
            Xs[(d + 0) * XS_STRIDE + m] = v.x;
            Xs[(d + 1) * XS_STRIDE + m] = v.y;
            Xs[(d + 2) * XS_STRIDE + m] = v.z;
            Xs[(d + 3) * XS_STRIDE + m] = v.w;
        }
    }

    float bestv[4] = {FLT_MAX, FLT_MAX, FLT_MAX, FLT_MAX};
    float secv[4]  = {FLT_MAX, FLT_MAX, FLT_MAX, FLT_MAX};
    int   besti[4] = {0, 0, 0, 0};

    for (int k0 = 0; k0 < KCB; k0 += BN) {
        __syncthreads();
        {
            int kk4 = tid & 15;
            int dr  = tid >> 4;
#pragma unroll
            for (int it = 0; it < 8; it++) {
                int d = it * 16 + dr;
                float4 v = *(const float4*)(E + (size_t)d * KCB + k0 + kk4 * 4);
                *(float4*)(Es + d * ES_STRIDE + kk4 * 4) = v;
            }
        }
        __syncthreads();

        float acc[4][4];
#pragma unroll
        for (int i = 0; i < 4; i++)
#pragma unroll
            for (int j = 0; j < 4; j++) acc[i][j] = 0.0f;

#pragma unroll 8
        for (int d = 0; d < DIM; d++) {
            float4 a = *(const float4*)(Xs + d * XS_STRIDE + ty * 4);
            float4 b = *(const float4*)(Es + d * ES_STRIDE + tx * 4);
            float av[4] = {a.x, a.y, a.z, a.w};
            float bv[4] = {b.x, b.y, b.z, b.w};
#pragma unroll
            for (int i = 0; i < 4; i++)
#pragma unroll
                for (int j = 0; j < 4; j++) acc[i][j] += av[i] * bv[j];
        }

        // Fused top-2 epilogue (j ascending k; strict < keeps first index)
#pragma unroll
        for (int j = 0; j < 4; j++) {
            int kk = k0 + tx * 4 + j;
            float en = g_enorm[kk];
#pragma unroll
            for (int i = 0; i < 4; i++) {
                float s = en - 2.0f * acc[i][j];
                if (s < bestv[i]) {
                    secv[i] = bestv[i];
                    bestv[i] = s; besti[i] = kk;
                } else if (s < secv[i]) {
                    secv[i] = s;
                }
            }
        }
    }

    // Cross-column reduction with top-2 margin
    __syncthreads();
    float* rv = smem;                          // [64][16] best values
    int*   ri = (int*)(rv + 64 * 16);          // [64][16] best indices
    float* rs = (float*)(ri + 64 * 16);        // [64][16] second values
#pragma unroll
    for (int i = 0; i < 4; i++) {
        rv[(ty * 4 + i) * 16 + tx] = bestv[i];
        ri[(ty * 4 + i) * 16 + tx] = besti[i];
        rs[(ty * 4 + i) * 16 + tx] = secv[i];
    }
    __syncthreads();
    if (tid < BM) {
        float bv = FLT_MAX; int bi = 0x7fffffff; float sec = FLT_MAX;
#pragma unroll
        for (int s = 0; s < 16; s++) {
            float v   = rv[tid * 16 + s];
            int   idx = ri[tid * 16 + s];
            float v2  = rs[tid * 16 + s];
            if (v < bv || (v == bv && idx < bi)) {
                sec = fminf(sec, bv);
                bv = v; bi = idx;
            } else {
                sec = fminf(sec, v);
            }
            sec = fminf(sec, v2);
        }
        int n = n0 + tid;
        g_code[n] = bi;
        out_code_f[n] = (float)bi;
        if (sec - bv < TIE_MARGIN) {
            int slot = atomicAdd(&g_nflag, 1);
            g_flag_rows[slot] = n;
        }
    }
}

// ---------------------------------------------------------------------------
// Pass 2: exact refinement for near-tie rows. Full fp64 distance over all
// 1024 codes, rounded to fp32 (matches the fp32 dist array the reference
// argmins over, incl. exact-tie -> lowest-index behavior).
// ---------------------------------------------------------------------------
__global__ __launch_bounds__(128)
void refine_kernel(const float* __restrict__ X, const float* __restrict__ E,
                   float* __restrict__ out_code_f) {
    __shared__ float  xs[DIM];
    __shared__ float  bvs[128];
    __shared__ int    bis[128];
    const int tid = threadIdx.x;
    const int nf = g_nflag;

    for (int f = blockIdx.x; f < nf; f += gridDim.x) {
        const int n = g_flag_rows[f];
        __syncthreads();
        xs[tid] = X[(size_t)n * DIM + tid];
        __syncthreads();

        float bv = FLT_MAX; int bi = 0x7fffffff;
        for (int k = tid; k < KCB; k += 128) {
            double s = 0.0;
#pragma unroll 8
            for (int d = 0; d < DIM; d++) {
                double dif = (double)xs[d] - (double)E[(size_t)d * KCB + k];
                s += dif * dif;
            }
            float sf = (float)s;
            if (sf < bv) { bv = sf; bi = k; }   // k ascending per thread
        }
        bvs[tid] = bv; bis[tid] = bi;
        __syncthreads();
#pragma unroll
        for (int s = 64; s > 0; s >>= 1) {
            if (tid < s) {
                if (bvs[tid + s] < bvs[tid] ||
                    (bvs[tid + s] == bvs[tid] && bis[tid + s] < bis[tid])) {
                    bvs[tid] = bvs[tid + s];
                    bis[tid] = bis[tid + s];
                }
            }
            __syncthreads();
        }
        if (tid == 0) {
            g_code[n] = bis[0];
            out_code_f[n] = (float)bis[0];
        }
        __syncthreads();
    }
}

// ---------------------------------------------------------------------------
// Gather quantize_st, commitment-loss partial, histogram, segment-sum scatter.
// ---------------------------------------------------------------------------
__global__ __launch_bounds__(256)
void gather_stats_kernel(const float* __restrict__ X, const float* __restrict__ E,
                         float* __restrict__ out) {
    const int t = threadIdx.x;
    const int n = blockIdx.x * 2 + (t >> 7);
    const int d = t & 127;
    const int c = g_code[n];

    float x = X[(size_t)n * DIM + d];
    float q = E[(size_t)d * KCB + c];
    float e = q - x;                       // stop_gradient(quantize - input)
    out[OFF_Q + (size_t)n * DIM + d] = x + e;   // straight-through, exact rounding
    float sq = e * e;

    atomicAdd(&g_emb_sum[d * KCB + c], x);
    if (d == 0) atomicAdd(&g_counts[c], 1.0f);

    __shared__ float red[256];
    red[t] = sq;
    __syncthreads();
#pragma unroll
    for (int s = 128; s > 0; s >>= 1) {
        if (t < s) red[t] += red[t + s];
        __syncthreads();
    }
    if (t == 0) atomicAdd(&g_diff, red[0]);
}

// ---------------------------------------------------------------------------
__global__ void finalize_cs_kernel(const float* __restrict__ cs_in,
                                   float* __restrict__ out) {
    int k = threadIdx.x;  // 1024 threads
    float ncs = cs_in[k] * DECAY + ONE_M_DECAY * g_counts[k];
    out[OFF_CS + k] = ncs;

    __shared__ float red[KCB];
    red[k] = ncs;
    __syncthreads();
    for (int s = 512; s > 0; s >>= 1) {
        if (k < s) red[k] += red[k + s];
        __syncthreads();
    }
    if (k == 0) {
        g_n = red[0];
        out[OFF_DIFF] = VQ_COMMIT * g_diff / (float)((size_t)NVEC * DIM);
    }
}

// ---------------------------------------------------------------------------
__global__ void finalize_emb_kernel(const float* __restrict__ mean_in,
                                    float* __restrict__ out) {
    int i = blockIdx.x * blockDim.x + threadIdx.x;
    if (i >= DIM * KCB) return;
    int k = i & (KCB - 1);
    float mean = mean_in[i] * DECAY + ONE_M_DECAY * g_emb_sum[i];
    out[OFF_MEAN + i] = mean;
    float ncs = out[OFF_CS + k];
    float n = g_n;
    float cs = (ncs + EPSV) / (n + (float)KCB * EPSV) * n;
    out[OFF_EMB + i] = mean / cs;
}

// ---------------------------------------------------------------------------
extern "C" void kernel_launch(void* const* d_in, const int* in_sizes, int n_in,
                              void* d_out, int out_size) {
    const float* X  = (const float*)d_in[0];   // input [B,T,D]
    const float* E  = (const float*)d_in[1];   // embedding [D,K]
    const float* CS = (const float*)d_in[2];   // cluster_size [K]
    const float* EM = (const float*)d_in[3];   // embedding_mean [D,K]
    float* out = (float*)d_out;

    cudaFuncSetAttribute(dist_kernel,
                         cudaFuncAttributeMaxDynamicSharedMemorySize, SMEM_BYTES);

    zero_kernel<<<(DIM*KCB + 255) / 256, 256>>>();
    enorm_kernel<<<KCB / 256, 256>>>(E);
    dist_kernel<<<NVEC / BM, 256, SMEM_BYTES>>>(X, E, out + OFF_CODE);
    refine_kernel<<<148, 128>>>(X, E, out + OFF_CODE);
    gather_stats_kernel<<<NVEC / 2, 256>>>(X, E, out);
    finalize_cs_kernel<<<1, KCB>>>(CS, out);
    finalize_emb_kernel<<<(DIM*KCB + 255) / 256, 256>>>(EM, out);
}

// round 5
// speedup vs baseline: 1.4759x; 1.4759x over previous
#include <cuda_runtime.h>
#include <cfloat>
#include <cstdint>

// Problem constants
#define DIM   128
#define KCB   1024
#define NVEC  65536           // B*T = 16*4096
#define DECAY 0.99f
#define ONE_M_DECAY 0.01f
#define EPSV  1e-5f
#define VQ_COMMIT 0.25f

// Near-tie refinement margin (pass-1 fp32 error ~3e-5; ~80x safety)
#define TIE_MARGIN 0.008f
// Candidate margin inside refine stage A (fp32 rescore error ~3e-5)
#define CAND_MARGIN 1e-3f
#define MAX_CAND 64

// GEMM tiling: BM=64 rows, BN=128 cols, 8 K-tiles, 4x8 microtile via FFMA2
#define BM 64
#define BN 128
#define XS_STRIDE 68          // padded transpose stride
#define ES_STRIDE 128         // floats (conflict-free for both phases)
#define SMEM_BYTES ((DIM*XS_STRIDE + DIM*ES_STRIDE) * 4)   // 100352 B

// Output layout (floats), tuple order of the reference
#define OFF_Q    0
#define OFF_DIFF (NVEC*DIM)
#define OFF_CODE (OFF_DIFF + 1)
#define OFF_EMB  (OFF_CODE + NVEC)
#define OFF_CS   (OFF_EMB + DIM*KCB)
#define OFF_MEAN (OFF_CS + KCB)

// Scratch (__device__ globals; no allocations allowed)
__device__ float g_enorm[KCB];
__device__ int   g_code[NVEC];
__device__ float g_counts[KCB];
__device__ float g_emb_sum[DIM*KCB];
__device__ float g_diff;
__device__ float g_n;
__device__ int   g_nflag;
__device__ int   g_flag_rows[NVEC];

// ---------------------------------------------------------------------------
// Packed f32x2 helpers (SASS FFMA2 — only reachable via PTX)
// ---------------------------------------------------------------------------
__device__ __forceinline__ void ffma2(unsigned long long& acc,
                                      unsigned long long a,
                                      unsigned long long b) {
    asm("fma.rn.f32x2 %0, %1, %2, %0;" : "+l"(acc) : "l"(a), "l"(b));
}
__device__ __forceinline__ unsigned long long dup2(float x) {
    unsigned long long r;
    asm("mov.b64 %0, {%1, %1};" : "=l"(r) : "f"(x));
    return r;
}
__device__ __forceinline__ void unpack2(unsigned long long v, float& lo, float& hi) {
    asm("mov.b64 {%0, %1}, %2;" : "=f"(lo), "=f"(hi) : "l"(v));
}

// ---------------------------------------------------------------------------
// Zero scratch (graph replayed; re-zero every launch)
// ---------------------------------------------------------------------------
__global__ void zero_kernel() {
    int i = blockIdx.x * blockDim.x + threadIdx.x;
    if (i < DIM*KCB) g_emb_sum[i] = 0.0f;
    if (i < KCB)     g_counts[i]  = 0.0f;
    if (i == 0) { g_diff = 0.0f; g_nflag = 0; }
}

// ---------------------------------------------------------------------------
// ||e_k||^2 per codebook column
// ---------------------------------------------------------------------------
__global__ void enorm_kernel(const float* __restrict__ E) {
    int k = blockIdx.x * blockDim.x + threadIdx.x;
    if (k >= KCB) return;
    float s = 0.0f;
#pragma unroll 8
    for (int d = 0; d < DIM; d++) {
        float v = E[(size_t)d * KCB + k];
        s += v * v;
    }
    g_enorm[k] = s;
}

// ---------------------------------------------------------------------------
// Pass 1: fp32 distance GEMM (FFMA2 packed) + fused top-2 argmin + flagging.
// score(n,k) = ||e_k||^2 - 2 x_n.e_k  (argmin-equivalent).
// 256 threads = 16x16; thread microtile 4 rows x 8 cols (4 packed pairs).
// ---------------------------------------------------------------------------
__global__ __launch_bounds__(256)
void dist_kernel(const float* __restrict__ X, const float* __restrict__ E,
                 float* __restrict__ out_code_f) {
    extern __shared__ float smem[];
    float* Xs = smem;                    // [DIM][XS_STRIDE] transposed X tile
    float* Es = smem + DIM * XS_STRIDE;  // [DIM][ES_STRIDE] E tile

    const int tid = threadIdx.x;
    const int tx = tid & 15;             // col group: 8 cols each
    const int ty = tid >> 4;             // row group: 4 rows each
    const int n0 = blockIdx.x * BM;

    // Load X tile transposed: Xs[d][m] = X[n0+m][d]
    {
        int m  = tid >> 2;
        int dq = tid & 3;
        const float4* src = (const float4*)(X + (size_t)(n0 + m) * DIM);
#pragma unroll
        for (int it = 0; it < 8; it++) {
            int d4 = it * 4 + dq;
            float4 v = src[d4];
            int d = d4 * 4;
            Xs[(d + 0) * XS_STRIDE + m] = v.x;
            Xs[(d + 1) * XS_STRIDE + m] = v.y;
            Xs[(d + 2) * XS_STRIDE + m] = v.z;
            Xs[(d + 3) * XS_STRIDE + m] = v.w;
        }
    }

    float bestv[4] = {FLT_MAX, FLT_MAX, FLT_MAX, FLT_MAX};
    float secv[4]  = {FLT_MAX, FLT_MAX, FLT_MAX, FLT_MAX};
    int   besti[4] = {0, 0, 0, 0};

    for (int k0 = 0; k0 < KCB; k0 += BN) {
        __syncthreads();
        // Load Es[d][c] = E[d][k0+c], c in [0,128): 16 float4 per thread, linear
        {
#pragma unroll
            for (int it = 0; it < 16; it++) {
                int l  = it * 256 + tid;
                int d  = l >> 5;         // 32 float4 per row
                int c4 = l & 31;
                float4 v = *(const float4*)(E + (size_t)d * KCB + k0 + c4 * 4);
                *(float4*)(Es + d * ES_STRIDE + c4 * 4) = v;
            }
        }
        __syncthreads();

        unsigned long long acc[4][4];    // [row i][pair p] packed 2 cols each
#pragma unroll
        for (int i = 0; i < 4; i++)
#pragma unroll
            for (int p = 0; p < 4; p++) acc[i][p] = 0ULL;

#pragma unroll 8
        for (int d = 0; d < DIM; d++) {
            float4 a = *(const float4*)(Xs + d * XS_STRIDE + ty * 4);
            // b pairs come pre-packed: 2x LDS.128 of double2
            double2 b01 = *(const double2*)(Es + d * ES_STRIDE + tx * 8);
            double2 b23 = *(const double2*)(Es + d * ES_STRIDE + tx * 8 + 4);
            unsigned long long b[4];
            b[0] = __double_as_longlong(b01.x);
            b[1] = __double_as_longlong(b01.y);
            b[2] = __double_as_longlong(b23.x);
            b[3] = __double_as_longlong(b23.y);
            unsigned long long ad[4];
            ad[0] = dup2(a.x); ad[1] = dup2(a.y);
            ad[2] = dup2(a.z); ad[3] = dup2(a.w);
#pragma unroll
            for (int i = 0; i < 4; i++)
#pragma unroll
                for (int p = 0; p < 4; p++)
                    ffma2(acc[i][p], ad[i], b[p]);
        }

        // Fused top-2 epilogue (j ascending -> lowest index kept on strict <)
#pragma unroll
        for (int i = 0; i < 4; i++) {
            float f[8];
#pragma unroll
            for (int p = 0; p < 4; p++) unpack2(acc[i][p], f[2*p], f[2*p+1]);
#pragma unroll
            for (int j = 0; j < 8; j++) {
                int kk = k0 + tx * 8 + j;
                float s = fmaf(-2.0f, f[j], g_enorm[kk]);
                if (s < bestv[i]) {
                    secv[i] = bestv[i];
                    bestv[i] = s; besti[i] = kk;
                } else if (s < secv[i]) {
                    secv[i] = s;
                }
            }
        }
    }

    // Cross-column (tx) reduction with top-2 margin
    __syncthreads();
    float* rv = smem;                          // [64][16] best values
    int*   ri = (int*)(rv + 64 * 16);          // [64][16] best indices
    float* rs = (float*)(ri + 64 * 16);        // [64][16] second values
#pragma unroll
    for (int i = 0; i < 4; i++) {
        rv[(ty * 4 + i) * 16 + tx] = bestv[i];
        ri[(ty * 4 + i) * 16 + tx] = besti[i];
        rs[(ty * 4 + i) * 16 + tx] = secv[i];
    }
    __syncthreads();
    if (tid < BM) {
        float bv = FLT_MAX; int bi = 0x7fffffff; float sec = FLT_MAX;
#pragma unroll
        for (int s = 0; s < 16; s++) {
            float v   = rv[tid * 16 + s];
            int   idx = ri[tid * 16 + s];
            float v2  = rs[tid * 16 + s];
            if (v < bv || (v == bv && idx < bi)) {
                sec = fminf(sec, bv);
                bv = v; bi = idx;
            } else {
                sec = fminf(sec, v);
            }
            sec = fminf(sec, v2);
        }
        int n = n0 + tid;
        g_code[n] = bi;
        out_code_f[n] = (float)bi;
        if (sec - bv < TIE_MARGIN) {
            int slot = atomicAdd(&g_nflag, 1);
            g_flag_rows[slot] = n;
        }
    }
}

// ---------------------------------------------------------------------------
// Pass 2: two-stage refinement for near-tie rows.
// Stage A (fp32): rescore all 1024 codes, collect candidates within
// CAND_MARGIN of the min. Stage B (fp64): exact distance on candidates only,
// rounded to fp32; lowest index wins ties.
// ---------------------------------------------------------------------------
__global__ __launch_bounds__(128)
void refine_kernel(const float* __restrict__ X, const float* __restrict__ E,
                   float* __restrict__ out_code_f) {
    __shared__ float  xs[DIM];
    __shared__ float  red[128];
    __shared__ int    cand[MAX_CAND];
    __shared__ int    ncand_s;
    __shared__ double dred[128];
    const int tid = threadIdx.x;
    const int nf = g_nflag;

    for (int f = blockIdx.x; f < nf; f += gridDim.x) {
        const int n = g_flag_rows[f];
        __syncthreads();
        xs[tid] = X[(size_t)n * DIM + tid];
        if (tid == 0) ncand_s = 0;
        __syncthreads();

        // Stage A: fp32 scores for 8 codes per thread (k = j*128 + tid)
        float sc[8];
#pragma unroll
        for (int j = 0; j < 8; j++) sc[j] = 0.0f;
        for (int d = 0; d < DIM; d++) {
            float xv = xs[d];
            const float* Ed = E + (size_t)d * KCB + tid;
#pragma unroll
            for (int j = 0; j < 8; j++)
                sc[j] = fmaf(xv, Ed[j * 128], sc[j]);
        }
        float mymin = FLT_MAX;
#pragma unroll
        for (int j = 0; j < 8; j++) {
            sc[j] = fmaf(-2.0f, sc[j], g_enorm[j * 128 + tid]);
            mymin = fminf(mymin, sc[j]);
        }
        red[tid] = mymin;
        __syncthreads();
#pragma unroll
        for (int s = 64; s > 0; s >>= 1) {
            if (tid < s) red[tid] = fminf(red[tid], red[tid + s]);
            __syncthreads();
        }
        float thr = red[0] + CAND_MARGIN;
        __syncthreads();
#pragma unroll
        for (int j = 0; j < 8; j++) {
            if (sc[j] <= thr) {
                int slot = atomicAdd(&ncand_s, 1);
                if (slot < MAX_CAND) cand[slot] = j * 128 + tid;
            }
        }
        __syncthreads();
        int nc = ncand_s < MAX_CAND ? ncand_s : MAX_CAND;

        // Stage B: exact fp64 on candidates, block-cooperative
        float bv = FLT_MAX; int bi = 0x7fffffff;   // live in thread 0
        for (int ci = 0; ci < nc; ci++) {
            int k = cand[ci];
            double dif = (double)xs[tid] - (double)E[(size_t)tid * KCB + k];
            dred[tid] = dif * dif;
            __syncthreads();
#pragma unroll
            for (int s = 64; s > 0; s >>= 1) {
                if (tid < s) dred[tid] += dred[tid + s];
                __syncthreads();
            }
            if (tid == 0) {
                float sf = (float)dred[0];
                if (sf < bv || (sf == bv && k < bi)) { bv = sf; bi = k; }
            }
            __syncthreads();
        }
        if (tid == 0) {
            g_code[n] = bi;
            out_code_f[n] = (float)bi;
        }
    }
}

// ---------------------------------------------------------------------------
// Gather quantize_st, commitment-loss partial, histogram, segment-sum scatter.
// ---------------------------------------------------------------------------
__global__ __launch_bounds__(256)
void gather_stats_kernel(const float* __restrict__ X, const float* __restrict__ E,
                         float* __restrict__ out) {
    const int t = threadIdx.x;
    const int n = blockIdx.x * 2 + (t >> 7);
    const int d = t & 127;
    const int c = g_code[n];

    float x = X[(size_t)n * DIM + d];
    float q = E[(size_t)d * KCB + c];
    float e = q - x;
    out[OFF_Q + (size_t)n * DIM + d] = x + e;   // straight-through rounding
    float sq = e * e;

    atomicAdd(&g_emb_sum[d * KCB + c], x);
    if (d == 0) atomicAdd(&g_counts[c], 1.0f);

    __shared__ float red[256];
    red[t] = sq;
    __syncthreads();
#pragma unroll
    for (int s = 128; s > 0; s >>= 1) {
        if (t < s) red[t] += red[t + s];
        __syncthreads();
    }
    if (t == 0) atomicAdd(&g_diff, red[0]);
}

// ---------------------------------------------------------------------------
__global__ void finalize_cs_kernel(const float* __restrict__ cs_in,
                                   float* __restrict__ out) {
    int k = threadIdx.x;  // 1024 threads
    float ncs = cs_in[k] * DECAY + ONE_M_DECAY * g_counts[k];
    out[OFF_CS + k] = ncs;

    __shared__ float red[KCB];
    red[k] = ncs;
    __syncthreads();
    for (int s = 512; s > 0; s >>= 1) {
        if (k < s) red[k] += red[k + s];
        __syncthreads();
    }
    if (k == 0) {
        g_n = red[0];
        out[OFF_DIFF] = VQ_COMMIT * g_diff / (float)((size_t)NVEC * DIM);
    }
}

// ---------------------------------------------------------------------------
__global__ void finalize_emb_kernel(const float* __restrict__ mean_in,
                                    float* __restrict__ out) {
    int i = blockIdx.x * blockDim.x + threadIdx.x;
    if (i >= DIM * KCB) return;
    int k = i & (KCB - 1);
    float mean = mean_in[i] * DECAY + ONE_M_DECAY * g_emb_sum[i];
    out[OFF_MEAN + i] = mean;
    float ncs = out[OFF_CS + k];
    float n = g_n;
    float cs = (ncs + EPSV) / (n + (float)KCB * EPSV) * n;
    out[OFF_EMB + i] = mean / cs;
}

// ---------------------------------------------------------------------------
extern "C" void kernel_launch(void* const* d_in, const int* in_sizes, int n_in,
                              void* d_out, int out_size) {
    const float* X  = (const float*)d_in[0];   // input [B,T,D]
    const float* E  = (const float*)d_in[1];   // embedding [D,K]
    const float* CS = (const float*)d_in[2];   // cluster_size [K]
    const float* EM = (const float*)d_in[3];   // embedding_mean [D,K]
    float* out = (float*)d_out;

    cudaFuncSetAttribute(dist_kernel,
                         cudaFuncAttributeMaxDynamicSharedMemorySize, SMEM_BYTES);

    zero_kernel<<<(DIM*KCB + 255) / 256, 256>>>();
    enorm_kernel<<<KCB / 256, 256>>>(E);
    dist_kernel<<<NVEC / BM, 256, SMEM_BYTES>>>(X, E, out + OFF_CODE);
    refine_kernel<<<148, 128>>>(X, E, out + OFF_CODE);
    gather_stats_kernel<<<NVEC / 2, 256>>>(X, E, out);
    finalize_cs_kernel<<<1, KCB>>>(CS, out);
    finalize_emb_kernel<<<(DIM*KCB + 255) / 256, 256>>>(EM, out);
}